// round 8
// baseline (speedup 1.0000x reference)
#include <cuda_runtime.h>
#include <cstdint>

#define BB     256
#define IN_F   1024
#define OUT_F  128
#define KD     16
#define NCOL   (OUT_F * KD)        // 2048
#define OUTW   (IN_F + OUT_F)      // 1152

#define SPLITS 8
#define KSPLIT (IN_F / SPLITS)     // 128
#define PSZ    (BB * NCOL)         // 524288
#define BM     64
#define BN     64
#define BKK    32
#define NKT    (KSPLIT / BKK)      // 4

// exp(-s) == +0.0f exactly for s >= 105; partial L1 sums are lower bounds,
// so screening on partial >= THRESH is lossless.
#define THRESH 105.0f

// GEMM partials [sp][o][b][k] (16 MB) + reduced m [o][b][k] (2 MB)
__device__ float d_part[SPLITS * PSZ];
__device__ float d_m2[PSZ];

__device__ __forceinline__ unsigned long long addx2(unsigned long long a,
                                                    unsigned long long b) {
    unsigned long long r;
    asm("add.rn.f32x2 %0, %1, %2;" : "=l"(r) : "l"(a), "l"(b));
    return r;
}

__device__ __forceinline__ void cp16(uint32_t smem, const void* gmem) {
    asm volatile("cp.async.cg.shared.global [%0], [%1], 16;"
                 :: "r"(smem), "l"(gmem));
}

// ---------------------------------------------------------------------------
// GEMM via mma.sync m16n8k8 tf32, split-K x8, transposed epilogue [o][b][k].
// grid (32, 4, 9): z<8 compute, z==8 x-copy + ZERO init of o_b region.
// ---------------------------------------------------------------------------
__global__ __launch_bounds__(128) void gemm_tf32_kernel(
    const float* __restrict__ A,
    const float* __restrict__ B,
    float* __restrict__ C,
    float* __restrict__ out)
{
    const int tid = threadIdx.x;

    if (blockIdx.z == SPLITS) {
        const int id = blockIdx.y * gridDim.x + blockIdx.x;  // 0..127
#pragma unroll
        for (int rr = 0; rr < 2; rr++) {
            const int r = id * 2 + rr;
            const float4* src = (const float4*)(A + r * IN_F);
            float4*       dst = (float4*)(out + r * OUTW);
            dst[tid]       = src[tid];
            dst[tid + 128] = src[tid + 128];
            if (tid < 32)   // diagonal never computed -> 0
                ((float4*)(out + r * OUTW + IN_F))[tid] =
                    make_float4(0.f, 0.f, 0.f, 0.f);
        }
        return;
    }

    __shared__ float As[2][BM * 36];
    __shared__ float Bs[2][BKK * 72];

    const int lane = tid & 31;
    const int wid  = tid >> 5;
    const int g    = lane >> 2;
    const int t    = lane & 3;
    const int wm   = (wid >> 1) * 32;
    const int wn   = (wid & 1) * 32;
    const int bm0  = blockIdx.y * BM;
    const int bn0  = blockIdx.x * BN;
    const int koff = blockIdx.z * KSPLIT;

    const int arow = tid >> 3;
    const int acol = (tid & 7) * 4;
    const int brow = tid >> 4;
    const int bcol = (tid & 15) * 4;

    uint32_t as_b[2], bs_b[2];
#pragma unroll
    for (int b = 0; b < 2; b++) {
        as_b[b] = (uint32_t)__cvta_generic_to_shared(&As[b][0]);
        bs_b[b] = (uint32_t)__cvta_generic_to_shared(&Bs[b][0]);
    }

    auto fetch = [&](int buf, int k0) {
#pragma unroll
        for (int i = 0; i < 4; i++)
            cp16(as_b[buf] + (((arow + i * 16) * 36 + acol) << 2),
                 &A[(bm0 + arow + i * 16) * IN_F + k0 + acol]);
#pragma unroll
        for (int i = 0; i < 4; i++)
            cp16(bs_b[buf] + (((brow + i * 8) * 72 + bcol) << 2),
                 &B[(k0 + brow + i * 8) * NCOL + bn0 + bcol]);
        asm volatile("cp.async.commit_group;");
    };

    float acc[2][4][4];
#pragma unroll
    for (int mf = 0; mf < 2; mf++)
#pragma unroll
        for (int nf = 0; nf < 4; nf++)
#pragma unroll
            for (int i = 0; i < 4; i++) acc[mf][nf][i] = 0.0f;

    fetch(0, koff);

#pragma unroll 1
    for (int kt = 0; kt < NKT; kt++) {
        if (kt + 1 < NKT) {
            fetch((kt + 1) & 1, koff + (kt + 1) * BKK);
            asm volatile("cp.async.wait_group 1;");
        } else {
            asm volatile("cp.async.wait_group 0;");
        }
        __syncthreads();
        const int cur = kt & 1;

#pragma unroll
        for (int ks = 0; ks < 4; ks++) {
            const int k = ks * 8;
            uint32_t ua[2][4], ub[4][2];
#pragma unroll
            for (int mf = 0; mf < 2; mf++) {
                const float* ap = &As[cur][(wm + mf * 16) * 36 + k];
                ua[mf][0] = __float_as_uint(ap[g * 36 + t]);
                ua[mf][1] = __float_as_uint(ap[(g + 8) * 36 + t]);
                ua[mf][2] = __float_as_uint(ap[g * 36 + t + 4]);
                ua[mf][3] = __float_as_uint(ap[(g + 8) * 36 + t + 4]);
            }
#pragma unroll
            for (int nf = 0; nf < 4; nf++) {
                const float* bp = &Bs[cur][k * 72 + wn + nf * 8 + g];
                ub[nf][0] = __float_as_uint(bp[t * 72]);
                ub[nf][1] = __float_as_uint(bp[(t + 4) * 72]);
            }
#pragma unroll
            for (int mf = 0; mf < 2; mf++)
#pragma unroll
                for (int nf = 0; nf < 4; nf++) {
                    asm volatile(
                        "mma.sync.aligned.m16n8k8.row.col.f32.tf32.tf32.f32 "
                        "{%0,%1,%2,%3}, {%4,%5,%6,%7}, {%8,%9}, {%0,%1,%2,%3};\n"
                        : "+f"(acc[mf][nf][0]), "+f"(acc[mf][nf][1]),
                          "+f"(acc[mf][nf][2]), "+f"(acc[mf][nf][3])
                        : "r"(ua[mf][0]), "r"(ua[mf][1]),
                          "r"(ua[mf][2]), "r"(ua[mf][3]),
                          "r"(ub[nf][0]), "r"(ub[nf][1]));
                }
        }
        __syncthreads();
    }

    float* Cz = C + blockIdx.z * PSZ;
#pragma unroll
    for (int mf = 0; mf < 2; mf++)
#pragma unroll
        for (int nf = 0; nf < 4; nf++) {
            const int r0 = bm0 + wm + mf * 16 + g;
            const int o  = ((bn0 + wn) >> 4) + (nf >> 1);
            const int k  = ((nf & 1) << 3) + t * 2;
            float* p = Cz + o * (BB * KD) + k;
            *(float2*)&p[r0 * KD] =
                make_float2(acc[mf][nf][0], acc[mf][nf][1]);
            *(float2*)&p[(r0 + 8) * KD] =
                make_float2(acc[mf][nf][2], acc[mf][nf][3]);
        }
}

// ---------------------------------------------------------------------------
// Reduce split-K partials: m = sum_sp part[sp]. Fully coalesced float4.
// grid 512 x 256 threads, one float4 per thread.
// ---------------------------------------------------------------------------
__global__ __launch_bounds__(256) void reduce_kernel(
    const float* __restrict__ part, float* __restrict__ m)
{
    const int idx = blockIdx.x * 256 + threadIdx.x;   // float4 index
    const float4* p = (const float4*)part;
    float4 acc = p[idx];
#pragma unroll
    for (int sp = 1; sp < SPLITS; sp++) {
        float4 v = p[idx + sp * (PSZ / 4)];
        acc.x += v.x; acc.y += v.y; acc.z += v.z; acc.w += v.w;
    }
    ((float4*)m)[idx] = acc;
}

// ---------------------------------------------------------------------------
// Pairwise exp(-L1), balanced cyclic triangle, 4 t-quarters.
// grid (128 o, 4 quarter), 256 threads; 32 iters/thread (quarter 3: 31+peel).
// Cooperative coalesced preamble into chunk-major negated smem.
// ---------------------------------------------------------------------------
__global__ __launch_bounds__(256) void pair_kernel(
    const float* __restrict__ m, float* __restrict__ out)
{
    __shared__ ulonglong2 sm2[4][BB];   // [chunk][b], negated rows, 16 KB

    const int o   = blockIdx.x;
    const int s   = blockIdx.y;         // t-quarter
    const int b1  = threadIdx.x;
    const unsigned long long SGN = 0x8000000080000000ULL;

    // cooperative coalesced load of the whole o-slice (256 rows x 64 B)
    const ulonglong2* mo = (const ulonglong2*)(m + (size_t)o * (BB * KD));
#pragma unroll
    for (int i = 0; i < 4; i++) {
        const int f = b1 + (i << 8);            // 16B-chunk index 0..1023
        ulonglong2 v = mo[f];
        v.x ^= SGN; v.y ^= SGN;
        sm2[f & 3][f >> 2] = v;
    }
    __syncthreads();

    // own (positive) row from smem
    unsigned long long a[8];
#pragma unroll
    for (int i = 0; i < 4; i++) {
        ulonglong2 v = sm2[i][b1];
        a[2 * i]     = v.x ^ SGN;
        a[2 * i + 1] = v.y ^ SGN;
    }

    const unsigned long long MSK = 0x7FFFFFFF7FFFFFFFULL;
    float* ob = out + IN_F + o;
    float tot = 0.0f;

    auto body = [&](int t) {
        const int b2 = (b1 + t) & 255;
        ulonglong2 c0 = sm2[0][b2], c1 = sm2[1][b2];
        unsigned long long d0 = addx2(a[0], c0.x) & MSK;
        unsigned long long d1 = addx2(a[1], c0.y) & MSK;
        unsigned long long d2 = addx2(a[2], c1.x) & MSK;
        unsigned long long d3 = addx2(a[3], c1.y) & MSK;
        unsigned long long f  = addx2(addx2(d0, d1), addx2(d2, d3));
        uint32_t flo, fhi;
        asm("mov.b64 {%0,%1}, %2;" : "=r"(flo), "=r"(fhi) : "l"(f));
        float s8 = __uint_as_float(flo) + __uint_as_float(fhi);

        if (s8 < THRESH) {               // else contribution is +0 exactly
            ulonglong2 c2 = sm2[2][b2], c3 = sm2[3][b2];
            unsigned long long d4 = addx2(a[4], c2.x) & MSK;
            unsigned long long d5 = addx2(a[5], c2.y) & MSK;
            unsigned long long d6 = addx2(a[6], c3.x) & MSK;
            unsigned long long d7 = addx2(a[7], c3.y) & MSK;
            unsigned long long g  = addx2(addx2(d4, d5), addx2(d6, d7));
            uint32_t glo, ghi;
            asm("mov.b64 {%0,%1}, %2;" : "=r"(glo), "=r"(ghi) : "l"(g));
            float s16 = s8 + __uint_as_float(glo) + __uint_as_float(ghi);
            float e = __expf(-s16);
            tot += e;
            if (e != 0.0f)               // credit the partner side
                atomicAdd(&ob[(size_t)b2 * OUTW], e);
        }
    };

    // quarters: t = 1+32s .. 32+32s  (s=3: ..127, then peel t=128 once)
    const int t0   = 1 + (s << 5);
    const int tend = (s == 3) ? 128 : t0 + 32;
#pragma unroll 4
    for (int t = t0; t < tend; t++) body(t);
    if (s == 3 && b1 < 128) body(128);   // distance-128 pairs, once

    if (tot != 0.0f)
        atomicAdd(&ob[(size_t)b1 * OUTW], tot);
}

extern "C" void kernel_launch(void* const* d_in, const int* in_sizes, int n_in,
                              void* d_out, int out_size)
{
    const float* x = (const float*)d_in[0];     // [256][1024]
    const float* t = (const float*)d_in[1];     // [1024][2048]
    float* out = (float*)d_out;                 // [256][1152]

    float* part;  cudaGetSymbolAddress((void**)&part, d_part);
    float* m;     cudaGetSymbolAddress((void**)&m, d_m2);

    dim3 ggrid(NCOL / BN, BB / BM, SPLITS + 1);  // (32, 4, 9)
    gemm_tf32_kernel<<<ggrid, 128>>>(x, t, part, out);
    reduce_kernel<<<PSZ / 4 / 256, 256>>>(part, m);
    pair_kernel<<<dim3(OUT_F, 4), 256>>>(m, out);
}